// round 17
// baseline (speedup 1.0000x reference)
#include <cuda_runtime.h>

// QuantizationLayer: out[b, 3n+i] = bit (2-i) of round_half_even(x[b,n]*8 - 0.5)
// x: [65536, 512] fp32 -> q in [0,7] -> 3 bits MSB-first as fp32 0/1.
//
// R16 kernel, resubmit (R16 bench was a GPU-acquisition timeout; never ran).
// ILP-2 variant of the proven R2/R12 shape. R15 proved streaming hints
// neutral (DRAM pinned at 76%); last untested lever is per-thread MLP.
// Each thread handles tiles t and t+half with BOTH LDG.128 issued up front
// (MLP_p1=2), then two staged/coalesced store sections. Same conflict-free
// smem pattern, same perfectly coalesced STG.128, 16384 one-shot CTAs.

__global__ void __launch_bounds__(256) quant_bits_kernel(
    const float4* __restrict__ in, float4* __restrict__ out, int half)
{
    __shared__ float4 stage[8][96];   // 8 warps * 96 float4 = 12 KB

    int warp = threadIdx.x >> 5;
    int lane = threadIdx.x & 31;

    int tA = blockIdx.x * blockDim.x + threadIdx.x;
    if (tA >= half) return;           // half % 256 == 0: whole warps exit
    int tB = tA + half;

    // Both loads in flight before any dependent work.
    float4 vA = __ldcs(in + tA);
    float4 vB = __ldcs(in + tB);

    // ---- tile A ----
    {
        int q0 = __float2int_rn(vA.x * 8.0f - 0.5f);
        int q1 = __float2int_rn(vA.y * 8.0f - 0.5f);
        int q2 = __float2int_rn(vA.z * 8.0f - 0.5f);
        int q3 = __float2int_rn(vA.w * 8.0f - 0.5f);

        float4 o0, o1, o2;
        o0.x = (float)((q0 >> 2) & 1);
        o0.y = (float)((q0 >> 1) & 1);
        o0.z = (float)( q0       & 1);
        o0.w = (float)((q1 >> 2) & 1);
        o1.x = (float)((q1 >> 1) & 1);
        o1.y = (float)( q1       & 1);
        o1.z = (float)((q2 >> 2) & 1);
        o1.w = (float)((q2 >> 1) & 1);
        o2.x = (float)( q2       & 1);
        o2.y = (float)((q3 >> 2) & 1);
        o2.z = (float)((q3 >> 1) & 1);
        o2.w = (float)( q3       & 1);

        stage[warp][3 * lane + 0] = o0;   // 48B/lane stride: conflict-free
        stage[warp][3 * lane + 1] = o1;
        stage[warp][3 * lane + 2] = o2;
        __syncwarp();

        int base = (tA >> 5) * 96;
        __stcs(&out[base + lane     ], stage[warp][lane     ]);
        __stcs(&out[base + lane + 32], stage[warp][lane + 32]);
        __stcs(&out[base + lane + 64], stage[warp][lane + 64]);
        __syncwarp();
    }

    // ---- tile B ----
    {
        int q0 = __float2int_rn(vB.x * 8.0f - 0.5f);
        int q1 = __float2int_rn(vB.y * 8.0f - 0.5f);
        int q2 = __float2int_rn(vB.z * 8.0f - 0.5f);
        int q3 = __float2int_rn(vB.w * 8.0f - 0.5f);

        float4 o0, o1, o2;
        o0.x = (float)((q0 >> 2) & 1);
        o0.y = (float)((q0 >> 1) & 1);
        o0.z = (float)( q0       & 1);
        o0.w = (float)((q1 >> 2) & 1);
        o1.x = (float)((q1 >> 1) & 1);
        o1.y = (float)( q1       & 1);
        o1.z = (float)((q2 >> 2) & 1);
        o1.w = (float)((q2 >> 1) & 1);
        o2.x = (float)( q2       & 1);
        o2.y = (float)((q3 >> 2) & 1);
        o2.z = (float)((q3 >> 1) & 1);
        o2.w = (float)( q3       & 1);

        stage[warp][3 * lane + 0] = o0;
        stage[warp][3 * lane + 1] = o1;
        stage[warp][3 * lane + 2] = o2;
        __syncwarp();

        int base = (tB >> 5) * 96;
        __stcs(&out[base + lane     ], stage[warp][lane     ]);
        __stcs(&out[base + lane + 32], stage[warp][lane + 32]);
        __stcs(&out[base + lane + 64], stage[warp][lane + 64]);
    }
}

extern "C" void kernel_launch(void* const* d_in, const int* in_sizes, int n_in,
                              void* d_out, int out_size)
{
    const float4* in = (const float4*)d_in[0];
    float4* out = (float4*)d_out;
    int n = in_sizes[0];          // 33,554,432 elements
    int n4 = n / 4;               // 8,388,608 float4 tiles
    int half = n4 / 2;            // 4,194,304 tiles per section

    int threads = 256;
    int blocks = (half + threads - 1) / threads;   // 16384 one-shot CTAs
    quant_bits_kernel<<<blocks, threads>>>(in, out, half);
}